// round 6
// baseline (speedup 1.0000x reference)
#include <cuda_runtime.h>
#include <cuda_bf16.h>
#include <cstdint>
#include <cstddef>

#define N_NODES 50000
#define N_EDGES 1000000
#define DIM     128
#define HID     64
#define TE      128
#define NT      7813       // ceil(1e6/128)
#define GRID_E  296

typedef unsigned long long u64;

extern __shared__ __align__(1024) unsigned char dynsmem[];

// Combined per-node projections: g_P[n][0:64] = PA, g_P[n][64:128] = PB (25.6MB)
__device__ __align__(16) float g_P[50048 * 128];

// ---------------- helpers ----------------
__device__ __forceinline__ uint32_t smem_u32(const void* p) {
    uint32_t a;
    asm("{ .reg .u64 t; cvta.to.shared.u64 t, %1; cvt.u32.u64 %0, t; }" : "=r"(a) : "l"(p));
    return a;
}
__device__ __forceinline__ void ldsm4(uint32_t* r, uint32_t a) {
    asm volatile("ldmatrix.sync.aligned.m8n8.x4.shared.b16 {%0,%1,%2,%3}, [%4];"
        : "=r"(r[0]), "=r"(r[1]), "=r"(r[2]), "=r"(r[3]) : "r"(a));
}
__device__ __forceinline__ void ldsm4t(uint32_t* r, uint32_t a) {
    asm volatile("ldmatrix.sync.aligned.m8n8.x4.trans.shared.b16 {%0,%1,%2,%3}, [%4];"
        : "=r"(r[0]), "=r"(r[1]), "=r"(r[2]), "=r"(r[3]) : "r"(a));
}
__device__ __forceinline__ void mma16816(float* c, const uint32_t* a,
                                         uint32_t b0, uint32_t b1) {
    asm volatile(
        "mma.sync.aligned.m16n8k16.row.col.f32.bf16.bf16.f32 "
        "{%0,%1,%2,%3}, {%4,%5,%6,%7}, {%8,%9}, {%0,%1,%2,%3};"
        : "+f"(c[0]), "+f"(c[1]), "+f"(c[2]), "+f"(c[3])
        : "r"(a[0]), "r"(a[1]), "r"(a[2]), "r"(a[3]), "r"(b0), "r"(b1));
}
__device__ __forceinline__ uint32_t pack_hi2(float x, float y) {
    return __byte_perm(__float_as_uint(x), __float_as_uint(y), 0x7632);
}
__device__ __forceinline__ float hi_of(float x) {
    return __uint_as_float(__float_as_uint(x) & 0xFFFF0000u);
}
__device__ __forceinline__ uint32_t pack_lo2(float x, float y) {
    float lx = x - hi_of(x), ly = y - hi_of(y);
    uint32_t r;
    asm("cvt.rn.bf16x2.f32 %0, %1, %2;" : "=r"(r) : "f"(ly), "f"(lx));
    return r;
}

// ---- edge-kernel smem offsets ----
#define OFF_W1HI 0        // [k:128][j:64] bf16, swz ((j>>3)^(k&7))
#define OFF_W1LO 16384
#define OFF_W2HI 32768    // [k:64][j:64]
#define OFF_W2LO 40960
#define OFF_EHI  49152    // e quarter [m:128][k:32], 64B rows, swz c^((m>>1)&3)
#define OFF_ELO  57344
#define OFF_PAB  65536    // [m:128] 256B rows; PAB f32 (16B-granule swz g^(m&7));
                          // aliased by h1: hi [0,128) chunk swz nt^(r&7), lo [128,256)
#define OFF_B1   98304
#define OFF_B2   98560
#define OFF_W3   98816
#define SMEM_EDGE 99072

// ---- prep-kernel smem offsets ----
#define P_WHI 0           // [k:128][j:64]
#define P_WLO 16384
#define P_XHI 32768       // x half [m:128][k:64], 128B rows, swz c^(m&7)
#define P_XLO 49152
#define SMEM_PREP 65536

// ============================================================================
// Prep: g_P[n][p*64 + j] = x[n] . W1[j][p*128 : p*128+128]  (split-bf16 MMA)
// One 128-node tile per block; 4 warps, 32 nodes/warp.
// ============================================================================
__global__ void __launch_bounds__(128, 2) prep_kernel(
    const float* __restrict__ x, const float* __restrict__ W1)
{
    unsigned char* smem = dynsmem;
    const uint32_t sbase = smem_u32(smem);
    const int tid  = threadIdx.x;
    const int lane = tid & 31;
    const int m0   = (tid >> 5) * 32;
    const int nbase = blockIdx.x * 128;

    #pragma unroll 1
    for (int p = 0; p < 2; p++) {
        for (int i = tid; i < 8192; i += 128) {
            int j = i >> 7, k = i & 127;
            float v = W1[j * 384 + p * 128 + k];
            uint32_t off = (uint32_t)(k * 128 + ((((j >> 3) ^ (k & 7)) << 4)) + (j & 7) * 2);
            *(unsigned short*)(smem + P_WHI + off) =
                (unsigned short)(__float_as_uint(v) >> 16);
            *(__nv_bfloat16*)(smem + P_WLO + off) = __float2bfloat16_rn(v - hi_of(v));
        }
        __syncthreads();

        float acc[2][8][4];
        #pragma unroll
        for (int mt = 0; mt < 2; mt++)
            #pragma unroll
            for (int nt = 0; nt < 8; nt++)
                #pragma unroll
                for (int q = 0; q < 4; q++) acc[mt][nt][q] = 0.f;

        #pragma unroll 1
        for (int kh = 0; kh < 2; kh++) {
            // stage x half [m:128][k:64] hi/lo
            #pragma unroll
            for (int i = 0; i < 16; i++) {
                int idx = i * 128 + tid;
                int m = idx >> 4, f4 = idx & 15;
                int node = nbase + m;
                float4 v = (node < N_NODES)
                    ? __ldg((const float4*)(x + (size_t)node * DIM + kh * 64) + f4)
                    : make_float4(0.f, 0.f, 0.f, 0.f);
                int c = f4 >> 1;
                uint32_t off = (uint32_t)(m * 128 + (((c ^ (m & 7)) << 4)) + (f4 & 1) * 8);
                *(uint2*)(smem + P_XHI + off) =
                    make_uint2(pack_hi2(v.x, v.y), pack_hi2(v.z, v.w));
                *(uint2*)(smem + P_XLO + off) =
                    make_uint2(pack_lo2(v.x, v.y), pack_lo2(v.z, v.w));
            }
            __syncthreads();

            #pragma unroll
            for (int kc = 0; kc < 4; kc++) {
                uint32_t ah[2][4], al[2][4];
                int ca = kc * 2 + (lane >> 4);
                #pragma unroll
                for (int mt = 0; mt < 2; mt++) {
                    int r = m0 + mt * 16 + (lane & 15);
                    uint32_t ao = (uint32_t)(r * 128 + (((ca ^ (r & 7)) << 4)));
                    ldsm4(ah[mt], sbase + P_XHI + ao);
                    ldsm4(al[mt], sbase + P_XLO + ao);
                }
                int krow = kh * 64 + kc * 16 + (lane & 15);
                #pragma unroll
                for (int np = 0; np < 4; np++) {
                    int g = 2 * np + (lane >> 4);
                    uint32_t bo = (uint32_t)(krow * 128 + (((g ^ (krow & 7)) << 4)));
                    uint32_t bh[4], bl[4];
                    ldsm4t(bh, sbase + P_WHI + bo);
                    ldsm4t(bl, sbase + P_WLO + bo);
                    #pragma unroll
                    for (int mt = 0; mt < 2; mt++) {
                        mma16816(acc[mt][2*np],     ah[mt], bh[0], bh[1]);
                        mma16816(acc[mt][2*np + 1], ah[mt], bh[2], bh[3]);
                        mma16816(acc[mt][2*np],     al[mt], bh[0], bh[1]);
                        mma16816(acc[mt][2*np + 1], al[mt], bh[2], bh[3]);
                        mma16816(acc[mt][2*np],     ah[mt], bl[0], bl[1]);
                        mma16816(acc[mt][2*np + 1], ah[mt], bl[2], bl[3]);
                    }
                }
            }
            __syncthreads();
        }

        // store to g_P (rows up to 50047 are in-bounds scratch)
        #pragma unroll
        for (int mt = 0; mt < 2; mt++) {
            int r0 = m0 + mt * 16 + (lane >> 2);
            #pragma unroll
            for (int nt = 0; nt < 8; nt++) {
                int j0 = nt * 8 + (lane & 3) * 2;
                size_t base0 = (size_t)(nbase + r0) * 128 + p * 64 + j0;
                size_t base1 = (size_t)(nbase + r0 + 8) * 128 + p * 64 + j0;
                *(float2*)(g_P + base0) = make_float2(acc[mt][nt][0], acc[mt][nt][1]);
                *(float2*)(g_P + base1) = make_float2(acc[mt][nt][2], acc[mt][nt][3]);
            }
        }
        __syncthreads();
    }
}

// ============================================================================
// Edge kernel — persistent split-bf16 mma.sync; 4 warps x 32 edges, 128/tile.
// ============================================================================
__global__ void __launch_bounds__(128, 2) edge_kernel(
    const int*   __restrict__ ei,
    const float* __restrict__ e,
    const float* __restrict__ W1,
    const float* __restrict__ b1,
    const float* __restrict__ W2,
    const float* __restrict__ b2,
    const float* __restrict__ W3,
    const float* __restrict__ b3,
    float*       __restrict__ out)
{
    unsigned char* smem = dynsmem;
    const uint32_t sbase = smem_u32(smem);
    const int tid  = threadIdx.x;
    const int lane = tid & 31;
    const int m0   = (tid >> 5) * 32;

    // ---- stage weights hi/lo once ----
    for (int i = tid; i < 8192; i += 128) {
        int j = i >> 7, k = i & 127;
        float v = W1[j * 384 + 256 + k];
        uint32_t off = (uint32_t)(k * 128 + ((((j >> 3) ^ (k & 7)) << 4)) + (j & 7) * 2);
        *(unsigned short*)(smem + OFF_W1HI + off) =
            (unsigned short)(__float_as_uint(v) >> 16);
        *(__nv_bfloat16*)(smem + OFF_W1LO + off) = __float2bfloat16_rn(v - hi_of(v));
    }
    for (int i = tid; i < 4096; i += 128) {
        int j = i >> 6, k = i & 63;
        float v = W2[j * 64 + k];
        uint32_t off = (uint32_t)(k * 128 + ((((j >> 3) ^ (k & 7)) << 4)) + (j & 7) * 2);
        *(unsigned short*)(smem + OFF_W2HI + off) =
            (unsigned short)(__float_as_uint(v) >> 16);
        *(__nv_bfloat16*)(smem + OFF_W2LO + off) = __float2bfloat16_rn(v - hi_of(v));
    }
    if (tid < 64) {
        ((float*)(smem + OFF_B1))[tid] = b1[tid];
        ((float*)(smem + OFF_B2))[tid] = b2[tid];
        ((float*)(smem + OFF_W3))[tid] = W3[tid];
    }
    const float b3v = __ldg(b3);
    __syncthreads();

    const float* sB2p = (const float*)(smem + OFF_B2);
    const float* sW3p = (const float*)(smem + OFF_W3);

    #pragma unroll 1
    for (int t = blockIdx.x; t < NT; t += GRID_E) {
        const int ebase = t * TE;

        // ---- stage PAB: row m = tid; PAB[m][j] = PA[src][j]+PB[dst][j]+b1[j]
        {
            int m = tid;
            int ge = ebase + m;
            bool ok = ge < N_EDGES;
            int s = ok ? __ldg(ei + ge) : 0;
            int d = ok ? __ldg(ei + N_EDGES + ge) : 0;
            const float4* pa = (const float4*)(g_P + (size_t)s * 128);
            const float4* pb = (const float4*)(g_P + (size_t)d * 128 + 64);
            const float4* bb = (const float4*)(smem + OFF_B1);
            #pragma unroll
            for (int q = 0; q < 16; q++) {
                float4 a = pa[q], b = pb[q], c = bb[q];
                float4 r = make_float4(a.x + b.x + c.x, a.y + b.y + c.y,
                                       a.z + b.z + c.z, a.w + b.w + c.w);
                uint32_t off = (uint32_t)(m * 256 + (((q ^ (m & 7)) << 4)));
                *(float4*)(smem + OFF_PAB + off) = r;
            }
        }

        float acc[2][8][4];
        #pragma unroll
        for (int mt = 0; mt < 2; mt++)
            #pragma unroll
            for (int nt = 0; nt < 8; nt++)
                #pragma unroll
                for (int q = 0; q < 4; q++) acc[mt][nt][q] = 0.f;

        // ---- layer 1: four k-quarters ----
        #pragma unroll 1
        for (int q = 0; q < 4; q++) {
            // stage e quarter [m:128][k:32]
            #pragma unroll
            for (int i = 0; i < 8; i++) {
                int idx = i * 128 + tid;
                int m = idx >> 3, f4 = idx & 7;
                int ge = ebase + m;
                float4 v = (ge < N_EDGES)
                    ? __ldg((const float4*)(e + (size_t)ge * DIM + q * 32) + f4)
                    : make_float4(0.f, 0.f, 0.f, 0.f);
                int c = f4 >> 1;
                uint32_t off = (uint32_t)(m * 64 + (((c ^ ((m >> 1) & 3)) << 4)) + (f4 & 1) * 8);
                *(uint2*)(smem + OFF_EHI + off) =
                    make_uint2(pack_hi2(v.x, v.y), pack_hi2(v.z, v.w));
                *(uint2*)(smem + OFF_ELO + off) =
                    make_uint2(pack_lo2(v.x, v.y), pack_lo2(v.z, v.w));
            }
            __syncthreads();

            #pragma unroll
            for (int kc = 0; kc < 2; kc++) {
                uint32_t ah[2][4], al[2][4];
                int ca = kc * 2 + (lane >> 4);
                #pragma unroll
                for (int mt = 0; mt < 2; mt++) {
                    int r = m0 + mt * 16 + (lane & 15);
                    uint32_t ao = (uint32_t)(r * 64 + (((ca ^ ((r >> 1) & 3)) << 4)));
                    ldsm4(ah[mt], sbase + OFF_EHI + ao);
                    ldsm4(al[mt], sbase + OFF_ELO + ao);
                }
                int krow = q * 32 + kc * 16 + (lane & 15);
                #pragma unroll
                for (int np = 0; np < 4; np++) {
                    int g = 2 * np + (lane >> 4);
                    uint32_t bo = (uint32_t)(krow * 128 + (((g ^ (krow & 7)) << 4)));
                    uint32_t bh[4], bl[4];
                    ldsm4t(bh, sbase + OFF_W1HI + bo);
                    ldsm4t(bl, sbase + OFF_W1LO + bo);
                    #pragma unroll
                    for (int mt = 0; mt < 2; mt++) {
                        mma16816(acc[mt][2*np],     ah[mt], bh[0], bh[1]);
                        mma16816(acc[mt][2*np + 1], ah[mt], bh[2], bh[3]);
                        mma16816(acc[mt][2*np],     al[mt], bh[0], bh[1]);
                        mma16816(acc[mt][2*np + 1], al[mt], bh[2], bh[3]);
                        mma16816(acc[mt][2*np],     ah[mt], bl[0], bl[1]);
                        mma16816(acc[mt][2*np + 1], ah[mt], bl[2], bl[3]);
                    }
                }
            }
            __syncthreads();   // done reading this quarter before restage
        }

        // ---- epilogue 1: +PAB, relu, split -> h1 (aliases PAB rows, warp-private)
        #pragma unroll
        for (int mt = 0; mt < 2; mt++) {
            int r0 = m0 + mt * 16 + (lane >> 2);
            int r1 = r0 + 8;
            float2 p0[8], p1[8];
            #pragma unroll
            for (int nt = 0; nt < 8; nt++) {
                int j0 = nt * 8 + (lane & 3) * 2;
                int jg = j0 >> 2;
                p0[nt] = *(const float2*)(smem + OFF_PAB + r0 * 256 +
                          (((jg ^ (r0 & 7)) << 4)) + (j0 & 3) * 4);
                p1[nt] = *(const float2*)(smem + OFF_PAB + r1 * 256 +
                          (((jg ^ (r1 & 7)) << 4)) + (j0 & 3) * 4);
            }
            __syncwarp();
            #pragma unroll
            for (int nt = 0; nt < 8; nt++) {
                float v0 = fmaxf(acc[mt][nt][0] + p0[nt].x, 0.f);
                float v1 = fmaxf(acc[mt][nt][1] + p0[nt].y, 0.f);
                float v2 = fmaxf(acc[mt][nt][2] + p1[nt].x, 0.f);
                float v3 = fmaxf(acc[mt][nt][3] + p1[nt].y, 0.f);
                uint32_t o0 = (uint32_t)(r0 * 256 + (((nt ^ (r0 & 7)) << 4)) + (lane & 3) * 4);
                uint32_t o1 = (uint32_t)(r1 * 256 + (((nt ^ (r1 & 7)) << 4)) + (lane & 3) * 4);
                *(uint32_t*)(smem + OFF_PAB + o0)       = pack_hi2(v0, v1);
                *(uint32_t*)(smem + OFF_PAB + o0 + 128) = pack_lo2(v0, v1);
                *(uint32_t*)(smem + OFF_PAB + o1)       = pack_hi2(v2, v3);
                *(uint32_t*)(smem + OFF_PAB + o1 + 128) = pack_lo2(v2, v3);
            }
        }
        __syncwarp();

        // ---- layer 2: K=64 over h1 ----
        #pragma unroll
        for (int mt = 0; mt < 2; mt++)
            #pragma unroll
            for (int nt = 0; nt < 8; nt++)
                #pragma unroll
                for (int qq = 0; qq < 4; qq++) acc[mt][nt][qq] = 0.f;

        #pragma unroll
        for (int kc = 0; kc < 4; kc++) {
            uint32_t ah[2][4], al[2][4];
            int ca = kc * 2 + (lane >> 4);
            #pragma unroll
            for (int mt = 0; mt < 2; mt++) {
                int r = m0 + mt * 16 + (lane & 15);
                uint32_t ao = (uint32_t)(r * 256 + (((ca ^ (r & 7)) << 4)));
                ldsm4(ah[mt], sbase + OFF_PAB + ao);
                ldsm4(al[mt], sbase + OFF_PAB + ao + 128);
            }
            int krow = kc * 16 + (lane & 15);
            #pragma unroll
            for (int np = 0; np < 4; np++) {
                int g = 2 * np + (lane >> 4);
                uint32_t bo = (uint32_t)(krow * 128 + (((g ^ (krow & 7)) << 4)));
                uint32_t bh[4], bl[4];
                ldsm4t(bh, sbase + OFF_W2HI + bo);
                ldsm4t(bl, sbase + OFF_W2LO + bo);
                #pragma unroll
                for (int mt = 0; mt < 2; mt++) {
                    mma16816(acc[mt][2*np],     ah[mt], bh[0], bh[1]);
                    mma16816(acc[mt][2*np + 1], ah[mt], bh[2], bh[3]);
                    mma16816(acc[mt][2*np],     al[mt], bh[0], bh[1]);
                    mma16816(acc[mt][2*np + 1], al[mt], bh[2], bh[3]);
                    mma16816(acc[mt][2*np],     ah[mt], bl[0], bl[1]);
                    mma16816(acc[mt][2*np + 1], ah[mt], bl[2], bl[3]);
                }
            }
        }

        // ---- epilogue 2: +b2, relu, dot W3, shfl-reduce, store ----
        #pragma unroll
        for (int mt = 0; mt < 2; mt++) {
            int r0 = m0 + mt * 16 + (lane >> 2);
            float pr0 = 0.f, pr1 = 0.f;
            #pragma unroll
            for (int nt = 0; nt < 8; nt++) {
                int j0 = nt * 8 + (lane & 3) * 2;
                float2 bb = *(const float2*)(sB2p + j0);
                float2 ww = *(const float2*)(sW3p + j0);
                pr0 = fmaf(fmaxf(acc[mt][nt][0] + bb.x, 0.f), ww.x, pr0);
                pr0 = fmaf(fmaxf(acc[mt][nt][1] + bb.y, 0.f), ww.y, pr0);
                pr1 = fmaf(fmaxf(acc[mt][nt][2] + bb.x, 0.f), ww.x, pr1);
                pr1 = fmaf(fmaxf(acc[mt][nt][3] + bb.y, 0.f), ww.y, pr1);
            }
            pr0 += __shfl_xor_sync(0xffffffffu, pr0, 1);
            pr0 += __shfl_xor_sync(0xffffffffu, pr0, 2);
            pr1 += __shfl_xor_sync(0xffffffffu, pr1, 1);
            pr1 += __shfl_xor_sync(0xffffffffu, pr1, 2);
            if ((lane & 3) == 0) {
                int ge0 = ebase + r0, ge1 = ebase + r0 + 8;
                if (ge0 < N_EDGES) out[ge0] = pr0 + b3v;
                if (ge1 < N_EDGES) out[ge1] = pr1 + b3v;
            }
        }
        __syncthreads();   // before next tile restages e/PAB
    }
}

// ============================================================================
extern "C" void kernel_launch(void* const* d_in, const int* in_sizes, int n_in,
                              void* d_out, int out_size)
{
    const int*   ei = (const int*)  d_in[0];
    const float* x  = (const float*)d_in[1];
    const float* e  = (const float*)d_in[2];
    const float* W1 = (const float*)d_in[3];
    const float* b1 = (const float*)d_in[4];
    const float* W2 = (const float*)d_in[5];
    const float* b2 = (const float*)d_in[6];
    const float* W3 = (const float*)d_in[7];
    const float* b3 = (const float*)d_in[8];
    float* out = (float*)d_out;

    (void)in_sizes; (void)n_in; (void)out_size;

    cudaFuncSetAttribute(prep_kernel,
                         cudaFuncAttributeMaxDynamicSharedMemorySize, SMEM_PREP);
    cudaFuncSetAttribute(edge_kernel,
                         cudaFuncAttributeMaxDynamicSharedMemorySize, SMEM_EDGE);

    prep_kernel<<<391, 128, SMEM_PREP>>>(x, W1);
    edge_kernel<<<GRID_E, 128, SMEM_EDGE>>>(ei, e, W1, b1, W2, b2, W3, b3, out);
}